// round 4
// baseline (speedup 1.0000x reference)
#include <cuda_runtime.h>
#include <math.h>

#define T_STEPS 64
#define BATCH   1024
#define OBSD    8
#define HID     512
#define TB      (T_STEPS * BATCH)   /* 65536 */
#define GATE3   (3 * HID)           /* 1536  */

#define BM  32
#define BKK 16

// ---------------- device scratch (allowed: static __device__ arrays) ----------
__device__ float g_H   [TB * HID];        // 128 MB  state h (init hs, then integrated in place)
__device__ float g_TMP [TB * HID];        // 128 MB  RK4 intermediate state
__device__ float g_KACC[TB * HID];        // 128 MB  k1 + 2k2 + 2k3 accumulator
__device__ float g_Z1  [TB * HID];        // 128 MB  ode layer1 activation
__device__ float g_Z2  [TB * HID];        // 128 MB  ode layer2 activation
__device__ float g_GI  [(size_t)TB * GATE3];  // 402 MB  gi = h_ode @ W_ih + b_ih (all t)
__device__ float g_GH  [BATCH * GATE3];   // 6 MB   gh for current GRU step
__device__ float g_HP0 [BATCH * HID];     // 2 MB   GRU hidden ping
__device__ float g_HP1 [BATCH * HID];     // 2 MB   GRU hidden pong

// ---------------- zero the GRU initial hidden state --------------------------
__global__ void zero_hp0_kernel() {
    int i = blockIdx.x * blockDim.x + threadIdx.x;
    if (i < BATCH * HID) g_HP0[i] = 0.f;
}

// ---------------- obs -> hidden: Linear(8,512) + LN + LeakyReLU --------------
__global__ void obs_kernel(const float* __restrict__ xs,
                           const float* __restrict__ W,
                           const float* __restrict__ b,
                           const float* __restrict__ lng,
                           const float* __restrict__ lnb) {
    int row = blockIdx.x;          // 0..TB-1
    int tid = threadIdx.x;         // 256 threads, 2 cols each
    __shared__ float xrow[OBSD];
    if (tid < OBSD) xrow[tid] = xs[row * OBSD + tid];
    __syncthreads();

    float y[2];
#pragma unroll
    for (int j = 0; j < 2; j++) {
        int c = tid + j * 256;
        float acc = b[c];
#pragma unroll
        for (int k = 0; k < OBSD; k++) acc += xrow[k] * W[k * HID + c];
        y[j] = acc;
    }
    // block LN reduction over 512 values
    float s = y[0] + y[1];
    float ss = y[0] * y[0] + y[1] * y[1];
#pragma unroll
    for (int o = 16; o > 0; o >>= 1) {
        s  += __shfl_xor_sync(0xffffffffu, s, o);
        ss += __shfl_xor_sync(0xffffffffu, ss, o);
    }
    __shared__ float rs[8], rss[8];
    int warp = tid >> 5, lane = tid & 31;
    if (lane == 0) { rs[warp] = s; rss[warp] = ss; }
    __syncthreads();
    if (warp == 0) {
        float a  = (lane < 8) ? rs[lane]  : 0.f;
        float b2 = (lane < 8) ? rss[lane] : 0.f;
#pragma unroll
        for (int o = 4; o > 0; o >>= 1) {
            a  += __shfl_xor_sync(0xffffffffu, a, o);
            b2 += __shfl_xor_sync(0xffffffffu, b2, o);
        }
        if (lane == 0) { rs[0] = a; rss[0] = b2; }
    }
    __syncthreads();
    float mean = rs[0] * (1.f / HID);
    float var  = rss[0] * (1.f / HID) - mean * mean;
    float inv  = rsqrtf(var + 1e-5f);
#pragma unroll
    for (int j = 0; j < 2; j++) {
        int c = tid + j * 256;
        float v = (y[j] - mean) * inv * lng[c] + lnb[c];
        v = v > 0.f ? v : 0.01f * v;
        g_H[(size_t)row * HID + c] = v;
    }
}

// ---------------- fused GEMM: C = A[M,512] @ W[512,*] + bias, with epilogues --
// CTA tile: 32 rows x 512 cols (full LN rows). 256 threads: ty=warp (8), tx=lane.
// Each thread: 4 rows x 16 cols (cols = tx*4 + j*128 + q).
//
// mode 0: out = leaky(LN(C + bias))                     (ode L1/L2; bias may add t*trow)
// mode 1: out[row*ldo + coff + c] = C + bias            (gi / gh plain projection)
// mode 2: f = C+bias; KACC = f;       TMP = H + 0.125 f (RK4 k1)
// mode 3: f = C+bias; KACC += 2 f;    TMP = H + 0.125 f (RK4 k2)
// mode 4: f = C+bias; KACC += 2 f;    TMP = H + 0.25  f (RK4 k3)
// mode 5: f = C+bias; H = H + (dt/6)(KACC + f)          (RK4 k4 + combine)
__global__ void gemm_kernel(const float* __restrict__ A,
                            const float* __restrict__ W, int ldw,
                            const float* __restrict__ bias,
                            const float* __restrict__ trow, float tval,
                            const float* __restrict__ lng,
                            const float* __restrict__ lnb,
                            float* __restrict__ out, int ldo,
                            float* __restrict__ Hb,
                            float* __restrict__ TMPb,
                            float* __restrict__ KACCb,
                            int mode) {
    __shared__ __align__(16) float As[BKK][BM];
    __shared__ __align__(16) float Bs[BKK * 512];

    int tid = threadIdx.x;
    int ty = tid >> 5;     // warp id 0..7  -> 4 rows each
    int tx = tid & 31;     // lane          -> 16 cols each
    int rowBase = blockIdx.x * BM;
    int coff = blockIdx.y * 512;

    float acc[4][16];
#pragma unroll
    for (int i = 0; i < 4; i++)
#pragma unroll
        for (int n = 0; n < 16; n++) acc[i][n] = 0.f;

    for (int k0 = 0; k0 < HID; k0 += BKK) {
        // load A tile (32 x 16) transposed into As[k][row]
        if (tid < 128) {
            int r = tid >> 2;
            int kq = tid & 3;
            const float4 v = *reinterpret_cast<const float4*>(
                &A[(size_t)(rowBase + r) * HID + k0 + kq * 4]);
            As[kq * 4 + 0][r] = v.x;
            As[kq * 4 + 1][r] = v.y;
            As[kq * 4 + 2][r] = v.z;
            As[kq * 4 + 3][r] = v.w;
        }
        // load B tile (16 x 512)
#pragma unroll
        for (int l = 0; l < 8; l++) {
            int idx = tid + l * 256;      // 0..2047
            int kk = idx >> 7;
            int cq = idx & 127;
            *reinterpret_cast<float4*>(&Bs[kk * 512 + cq * 4]) =
                *reinterpret_cast<const float4*>(
                    &W[(size_t)(k0 + kk) * ldw + coff + cq * 4]);
        }
        __syncthreads();
#pragma unroll
        for (int kk = 0; kk < BKK; kk++) {
            float4 a = *reinterpret_cast<float4*>(&As[kk][ty * 4]);
            float av[4] = {a.x, a.y, a.z, a.w};
            float4 bf[4];
#pragma unroll
            for (int j = 0; j < 4; j++)
                bf[j] = *reinterpret_cast<float4*>(&Bs[kk * 512 + tx * 4 + j * 128]);
#pragma unroll
            for (int i = 0; i < 4; i++) {
#pragma unroll
                for (int j = 0; j < 4; j++) {
                    acc[i][j * 4 + 0] += av[i] * bf[j].x;
                    acc[i][j * 4 + 1] += av[i] * bf[j].y;
                    acc[i][j * 4 + 2] += av[i] * bf[j].z;
                    acc[i][j * 4 + 3] += av[i] * bf[j].w;
                }
            }
        }
        __syncthreads();
    }

    // bias values for this thread's 16 columns
    float bv[16];
#pragma unroll
    for (int j = 0; j < 4; j++)
#pragma unroll
        for (int q = 0; q < 4; q++) {
            int c = coff + tx * 4 + j * 128 + q;
            float b = bias[c];
            if (trow) b += tval * trow[c];
            bv[j * 4 + q] = b;
        }

    if (mode == 0) {
        // fused LayerNorm (over full 512-col row held by one warp) + leaky relu
#pragma unroll
        for (int i = 0; i < 4; i++) {
            float s = 0.f, ss = 0.f;
#pragma unroll
            for (int n = 0; n < 16; n++) {
                float v = acc[i][n] + bv[n];
                acc[i][n] = v;
                s += v; ss += v * v;
            }
#pragma unroll
            for (int o = 16; o > 0; o >>= 1) {
                s  += __shfl_xor_sync(0xffffffffu, s, o);
                ss += __shfl_xor_sync(0xffffffffu, ss, o);
            }
            float mean = s * (1.f / HID);
            float inv  = rsqrtf(ss * (1.f / HID) - mean * mean + 1e-5f);
            size_t base = (size_t)(rowBase + ty * 4 + i) * HID;
#pragma unroll
            for (int j = 0; j < 4; j++)
#pragma unroll
                for (int q = 0; q < 4; q++) {
                    int cl = tx * 4 + j * 128 + q;
                    float v = (acc[i][j * 4 + q] - mean) * inv * lng[cl] + lnb[cl];
                    out[base + cl] = v > 0.f ? v : 0.01f * v;
                }
        }
    } else if (mode == 1) {
#pragma unroll
        for (int i = 0; i < 4; i++) {
            size_t base = (size_t)(rowBase + ty * 4 + i) * ldo + coff;
#pragma unroll
            for (int j = 0; j < 4; j++)
#pragma unroll
                for (int q = 0; q < 4; q++) {
                    int cl = tx * 4 + j * 128 + q;
                    out[base + cl] = acc[i][j * 4 + q] + bv[j * 4 + q];
                }
        }
    } else {
        // RK4 epilogues
#pragma unroll
        for (int i = 0; i < 4; i++) {
            size_t base = (size_t)(rowBase + ty * 4 + i) * HID;
#pragma unroll
            for (int j = 0; j < 4; j++)
#pragma unroll
                for (int q = 0; q < 4; q++) {
                    int cl = tx * 4 + j * 128 + q;
                    float f = acc[i][j * 4 + q] + bv[j * 4 + q];
                    float h = Hb[base + cl];
                    if (mode == 2) {
                        KACCb[base + cl] = f;
                        TMPb[base + cl] = h + 0.125f * f;
                    } else if (mode == 3) {
                        KACCb[base + cl] += 2.f * f;
                        TMPb[base + cl] = h + 0.125f * f;
                    } else if (mode == 4) {
                        KACCb[base + cl] += 2.f * f;
                        TMPb[base + cl] = h + 0.25f * f;
                    } else {
                        Hb[base + cl] = h + (0.25f / 6.f) * (KACCb[base + cl] + f);
                    }
                }
        }
    }
}

// ---------------- GRU gate fusion -------------------------------------------
__global__ void gates_kernel(int t, const float* __restrict__ hp,
                             float* __restrict__ hn, float* __restrict__ dout) {
    int idx = blockIdx.x * blockDim.x + threadIdx.x;
    if (idx >= BATCH * HID) return;
    int r = idx >> 9;
    int c = idx & 511;
    size_t gib = ((size_t)t * BATCH + r) * GATE3;
    size_t ghb = (size_t)r * GATE3;
    float ir = g_GI[gib + c], iz = g_GI[gib + c + HID], in_ = g_GI[gib + c + 2 * HID];
    float hr = g_GH[ghb + c], hz = g_GH[ghb + c + HID], hnn = g_GH[ghb + c + 2 * HID];
    float rg = 1.f / (1.f + expf(-(ir + hr)));
    float zg = 1.f / (1.f + expf(-(iz + hz)));
    float ng = tanhf(in_ + rg * hnn);
    float h  = hp[idx];
    float v  = (1.f - zg) * ng + zg * h;
    hn[idx] = v;
    if (dout) dout[idx] = v;
}

// ---------------- host orchestration ----------------------------------------
extern "C" void kernel_launch(void* const* d_in, const int* in_sizes, int n_in,
                              void* d_out, int out_size) {
    const float* xs       = (const float*)d_in[0];
    const float* obs_W    = (const float*)d_in[1];
    const float* obs_b    = (const float*)d_in[2];
    const float* obs_ln_g = (const float*)d_in[3];
    const float* obs_ln_b = (const float*)d_in[4];
    const float* ode_W1   = (const float*)d_in[5];   // [513,512]
    const float* ode_b1   = (const float*)d_in[6];
    const float* ode_ln1g = (const float*)d_in[7];
    const float* ode_ln1b = (const float*)d_in[8];
    const float* ode_W2   = (const float*)d_in[9];
    const float* ode_b2   = (const float*)d_in[10];
    const float* ode_ln2g = (const float*)d_in[11];
    const float* ode_ln2b = (const float*)d_in[12];
    const float* ode_Wout = (const float*)d_in[13];
    const float* ode_bout = (const float*)d_in[14];
    const float* W_ih     = (const float*)d_in[15];  // [512,1536]
    const float* b_ih     = (const float*)d_in[16];
    const float* W_hh     = (const float*)d_in[17];
    const float* b_hh     = (const float*)d_in[18];

    float *pH, *pTMP, *pKACC, *pZ1, *pZ2, *pGI, *pGH, *pHP0, *pHP1;
    cudaGetSymbolAddress((void**)&pH,    g_H);
    cudaGetSymbolAddress((void**)&pTMP,  g_TMP);
    cudaGetSymbolAddress((void**)&pKACC, g_KACC);
    cudaGetSymbolAddress((void**)&pZ1,   g_Z1);
    cudaGetSymbolAddress((void**)&pZ2,   g_Z2);
    cudaGetSymbolAddress((void**)&pGI,   g_GI);
    cudaGetSymbolAddress((void**)&pGH,   g_GH);
    cudaGetSymbolAddress((void**)&pHP0,  g_HP0);
    cudaGetSymbolAddress((void**)&pHP1,  g_HP1);

    zero_hp0_kernel<<<(BATCH * HID + 255) / 256, 256>>>();

    // hs for all timesteps at once -> g_H
    obs_kernel<<<TB, 256>>>(xs, obs_W, obs_b, obs_ln_g, obs_ln_b);

    // Batched RK4 over all T*B rows: 4 steps x 4 evals x 3 GEMM phases
    const float dt = 0.25f;
    const float* trow = ode_W1 + (size_t)512 * 512;   // the time row of W1
    dim3 gOde(TB / BM, 1);
    for (int s = 0; s < 4; s++) {
        float t0 = s * dt;
        const float* Ain[4] = {pH, pTMP, pTMP, pTMP};
        float tv[4] = {t0, t0 + 0.125f, t0 + 0.125f, t0 + 0.25f};
        int km[4] = {2, 3, 4, 5};
        for (int e = 0; e < 4; e++) {
            gemm_kernel<<<gOde, 256>>>(Ain[e], ode_W1, 512, ode_b1, trow, tv[e],
                                       ode_ln1g, ode_ln1b, pZ1, HID,
                                       nullptr, nullptr, nullptr, 0);
            gemm_kernel<<<gOde, 256>>>(pZ1, ode_W2, 512, ode_b2, nullptr, 0.f,
                                       ode_ln2g, ode_ln2b, pZ2, HID,
                                       nullptr, nullptr, nullptr, 0);
            gemm_kernel<<<gOde, 256>>>(pZ2, ode_Wout, 512, ode_bout, nullptr, 0.f,
                                       nullptr, nullptr, nullptr, HID,
                                       pH, pTMP, pKACC, km[e]);
        }
    }

    // gi = h_ode @ W_ih + b_ih for all timesteps in one GEMM
    gemm_kernel<<<dim3(TB / BM, 3), 256>>>(pH, W_ih, GATE3, b_ih, nullptr, 0.f,
                                           nullptr, nullptr, pGI, GATE3,
                                           nullptr, nullptr, nullptr, 1);

    // Sequential GRU over 64 timesteps
    for (int t = 0; t < T_STEPS; t++) {
        float* hp = (t & 1) ? pHP1 : pHP0;
        float* hn = (t & 1) ? pHP0 : pHP1;
        gemm_kernel<<<dim3(BATCH / BM, 3), 256>>>(hp, W_hh, GATE3, b_hh,
                                                  nullptr, 0.f, nullptr, nullptr,
                                                  pGH, GATE3,
                                                  nullptr, nullptr, nullptr, 1);
        gates_kernel<<<(BATCH * HID + 255) / 256, 256>>>(
            t, hp, hn, (t == T_STEPS - 1) ? (float*)d_out : nullptr);
    }
}

// round 8
// speedup vs baseline: 1.7710x; 1.7710x over previous
#include <cuda_runtime.h>
#include <cuda_bf16.h>
#include <stdint.h>
#include <cstdint>
#include <math.h>

#define T_STEPS 64
#define BATCH   1024
#define OBSD    8
#define HID     512
#define TB      (T_STEPS * BATCH)   /* 65536 */
#define GATE3   (3 * HID)           /* 1536  */

typedef __nv_bfloat16 bf16;

// ---------------- fp32 state ------------------------------------------------
__device__ __align__(128) float g_H   [TB * HID];        // RK4 state (fp32 master)
__device__ __align__(128) float g_KACC[TB * HID];        // k1+2k2+2k3
__device__ __align__(128) float g_GI  [(size_t)TB * GATE3];
__device__ __align__(128) float g_GH  [BATCH * GATE3];
__device__ __align__(128) float g_HP0 [BATCH * HID];
__device__ __align__(128) float g_HP1 [BATCH * HID];

// ---------------- bf16 hi/lo activation planes ------------------------------
__device__ __align__(128) bf16 g_Hh [TB * HID], g_Hl [TB * HID];
__device__ __align__(128) bf16 g_Th [TB * HID], g_Tl [TB * HID];   // RK4 tmp state
__device__ __align__(128) bf16 g_Z1h[TB * HID], g_Z1l[TB * HID];
__device__ __align__(128) bf16 g_Z2h[TB * HID], g_Z2l[TB * HID];
__device__ __align__(128) bf16 g_P0h[BATCH * HID], g_P0l[BATCH * HID];
__device__ __align__(128) bf16 g_P1h[BATCH * HID], g_P1l[BATCH * HID];

// ---------------- bf16 hi/lo weight planes ----------------------------------
__device__ __align__(128) bf16 g_W1h[HID * HID],   g_W1l[HID * HID];
__device__ __align__(128) bf16 g_W2h[HID * HID],   g_W2l[HID * HID];
__device__ __align__(128) bf16 g_Woh[HID * HID],   g_Wol[HID * HID];
__device__ __align__(128) bf16 g_Wih_h[HID * GATE3], g_Wih_l[HID * GATE3];
__device__ __align__(128) bf16 g_Whh_h[HID * GATE3], g_Whh_l[HID * GATE3];

// ---------------- helpers ----------------------------------------------------
__device__ __forceinline__ void store_planes(bf16* __restrict__ ph,
                                             bf16* __restrict__ pl,
                                             size_t idx, float a, float b) {
    bf16 ah = __float2bfloat16(a);
    bf16 bh = __float2bfloat16(b);
    float ar = a - __bfloat162float(ah);
    float br = b - __bfloat162float(bh);
    __nv_bfloat162 vh; vh.x = ah; vh.y = bh;
    __nv_bfloat162 vl; vl.x = __float2bfloat16(ar); vl.y = __float2bfloat16(br);
    *reinterpret_cast<__nv_bfloat162*>(ph + idx) = vh;
    *reinterpret_cast<__nv_bfloat162*>(pl + idx) = vl;
}

__device__ __forceinline__ void mma16816(float* d, const unsigned* a, const unsigned* b) {
    asm volatile(
        "mma.sync.aligned.m16n8k16.row.col.f32.bf16.bf16.f32 "
        "{%0,%1,%2,%3},{%4,%5,%6,%7},{%8,%9},{%0,%1,%2,%3};\n"
        : "+f"(d[0]), "+f"(d[1]), "+f"(d[2]), "+f"(d[3])
        : "r"(a[0]), "r"(a[1]), "r"(a[2]), "r"(a[3]), "r"(b[0]), "r"(b[1]));
}

__device__ __forceinline__ void ldsm4(unsigned* r, uint32_t addr) {
    asm volatile("ldmatrix.sync.aligned.m8n8.x4.shared.b16 {%0,%1,%2,%3},[%4];\n"
                 : "=r"(r[0]), "=r"(r[1]), "=r"(r[2]), "=r"(r[3]) : "r"(addr));
}
__device__ __forceinline__ void ldsm4t(unsigned* r, uint32_t addr) {
    asm volatile("ldmatrix.sync.aligned.m8n8.x4.trans.shared.b16 {%0,%1,%2,%3},[%4];\n"
                 : "=r"(r[0]), "=r"(r[1]), "=r"(r[2]), "=r"(r[3]) : "r"(addr));
}
__device__ __forceinline__ void cp16(uint32_t d, const void* s) {
    asm volatile("cp.async.cg.shared.global [%0], [%1], 16;\n" :: "r"(d), "l"(s));
}

// ---------------- weight split: fp32 -> (hi, lo) bf16 planes -----------------
__global__ void split_kernel(const float* __restrict__ src,
                             bf16* __restrict__ hi, bf16* __restrict__ lo, int n) {
    int i = blockIdx.x * blockDim.x + threadIdx.x;
    if (i < n) {
        float x = src[i];
        bf16 h = __float2bfloat16(x);
        hi[i] = h;
        lo[i] = __float2bfloat16(x - __bfloat162float(h));
    }
}

// ---------------- zero the GRU initial hidden state --------------------------
__global__ void zero_hp0_kernel() {
    int i = blockIdx.x * blockDim.x + threadIdx.x;
    if (i < BATCH * HID) {
        g_HP0[i] = 0.f;
        g_P0h[i] = __float2bfloat16(0.f);
        g_P0l[i] = __float2bfloat16(0.f);
    }
}

// ---------------- obs -> hidden: Linear(8,512) + LN + LeakyReLU --------------
__global__ void obs_kernel(const float* __restrict__ xs,
                           const float* __restrict__ W,
                           const float* __restrict__ b,
                           const float* __restrict__ lng,
                           const float* __restrict__ lnb) {
    int row = blockIdx.x;
    int tid = threadIdx.x;         // 256 threads, 2 cols each
    __shared__ float xrow[OBSD];
    if (tid < OBSD) xrow[tid] = xs[row * OBSD + tid];
    __syncthreads();

    float y[2];
#pragma unroll
    for (int j = 0; j < 2; j++) {
        int c = tid + j * 256;
        float acc = b[c];
#pragma unroll
        for (int k = 0; k < OBSD; k++) acc += xrow[k] * W[k * HID + c];
        y[j] = acc;
    }
    float s = y[0] + y[1];
    float ss = y[0] * y[0] + y[1] * y[1];
#pragma unroll
    for (int o = 16; o > 0; o >>= 1) {
        s  += __shfl_xor_sync(0xffffffffu, s, o);
        ss += __shfl_xor_sync(0xffffffffu, ss, o);
    }
    __shared__ float rs[8], rss[8];
    int warp = tid >> 5, lane = tid & 31;
    if (lane == 0) { rs[warp] = s; rss[warp] = ss; }
    __syncthreads();
    if (warp == 0) {
        float a  = (lane < 8) ? rs[lane]  : 0.f;
        float b2 = (lane < 8) ? rss[lane] : 0.f;
#pragma unroll
        for (int o = 4; o > 0; o >>= 1) {
            a  += __shfl_xor_sync(0xffffffffu, a, o);
            b2 += __shfl_xor_sync(0xffffffffu, b2, o);
        }
        if (lane == 0) { rs[0] = a; rss[0] = b2; }
    }
    __syncthreads();
    float mean = rs[0] * (1.f / HID);
    float var  = rss[0] * (1.f / HID) - mean * mean;
    float inv  = rsqrtf(var + 1e-5f);
#pragma unroll
    for (int j = 0; j < 2; j++) {
        int c = tid + j * 256;
        float v = (y[j] - mean) * inv * lng[c] + lnb[c];
        v = v > 0.f ? v : 0.01f * v;
        size_t idx = (size_t)row * HID + c;
        g_H[idx] = v;
        bf16 h = __float2bfloat16(v);
        g_Hh[idx] = h;
        g_Hl[idx] = __float2bfloat16(v - __bfloat162float(h));
    }
}

// ---------------- tensor-core GEMM, 3-MMA bf16 split, fused epilogues --------
// CTA tile 32 x 512, 8 warps (each m32 x n64), BK=16 double-buffered cp.async.
// modes: 0 = LN+leaky -> planes (Z); 1 = fp32 out (GI/GH);
//        2..5 = RK4 k1..k4 epilogues (TMP planes / H update, fp32 state).
#define SMEM_BUF_BYTES 36352   /* A: 2*32*24*2 = 3072, B: 2*16*520*2 = 33280 */
#define SMEM_TOTAL_BYTES (2 * SMEM_BUF_BYTES)

__device__ __forceinline__ void load_chunk(uint32_t smb, int buf, int k0,
                                           const bf16* Ah, const bf16* Al,
                                           const bf16* Wh, const bf16* Wl,
                                           int ldw, int coff, int rowBase, int tid) {
    uint32_t aoff = smb + buf * SMEM_BUF_BYTES;
    uint32_t boff = aoff + 3072;
#pragma unroll
    for (int l = 0; l < 8; l++) {
        int idx = tid + l * 256;          // 0..2047
        int p   = idx >> 10;
        int rem = idx & 1023;
        int kr  = rem >> 6;
        int u   = rem & 63;
        const bf16* src = (p ? Wl : Wh) + (size_t)(k0 + kr) * ldw + coff + u * 8;
        cp16(boff + ((p * 16 + kr) * 520 + u * 8) * 2, src);
    }
    if (tid < 128) {
        int p   = tid >> 6;
        int rem = tid & 63;
        int r   = rem >> 1;
        int u   = rem & 1;
        const bf16* src = (p ? Al : Ah) + (size_t)(rowBase + r) * HID + k0 + u * 8;
        cp16(aoff + ((p * 32 + r) * 24 + u * 8) * 2, src);
    }
    asm volatile("cp.async.commit_group;\n" ::: "memory");
}

extern __shared__ char dyn_sm[];

__global__ void __launch_bounds__(256, 1)
gemm_mma(const bf16* __restrict__ Ah, const bf16* __restrict__ Al,
         const bf16* __restrict__ Wh, const bf16* __restrict__ Wl, int ldw,
         const float* __restrict__ bias,
         const float* __restrict__ trow, float tval,
         const float* __restrict__ lng, const float* __restrict__ lnb,
         float* __restrict__ out, int ldo,
         bf16* __restrict__ outh, bf16* __restrict__ outl,
         float* __restrict__ Hb, float* __restrict__ KACCb,
         int mode) {
    int tid  = threadIdx.x;
    int w    = tid >> 5;
    int lane = tid & 31;
    int g    = lane >> 2;
    int tig  = lane & 3;
    int rowBase = blockIdx.x * 32;
    int coff    = blockIdx.y * 512;

    uint32_t smb = (uint32_t)__cvta_generic_to_shared(dyn_sm);

    float acc[2][8][4];
#pragma unroll
    for (int i = 0; i < 2; i++)
#pragma unroll
        for (int j = 0; j < 8; j++)
#pragma unroll
            for (int q = 0; q < 4; q++) acc[i][j][q] = 0.f;

    const int NC = HID / 16;   // 32
    load_chunk(smb, 0, 0, Ah, Al, Wh, Wl, ldw, coff, rowBase, tid);

#pragma unroll 1
    for (int c = 0; c < NC; c++) {
        if (c + 1 < NC) {
            load_chunk(smb, (c + 1) & 1, (c + 1) * 16, Ah, Al, Wh, Wl, ldw, coff, rowBase, tid);
            asm volatile("cp.async.wait_group 1;\n" ::: "memory");
        } else {
            asm volatile("cp.async.wait_group 0;\n" ::: "memory");
        }
        __syncthreads();

        uint32_t aoff = smb + (c & 1) * SMEM_BUF_BYTES;
        uint32_t boff = aoff + 3072;

        unsigned af[2][2][4];   // [mtile][plane][4]
#pragma unroll
        for (int i = 0; i < 2; i++)
#pragma unroll
            for (int p = 0; p < 2; p++) {
                uint32_t ad = aoff + ((p * 32 + i * 16 + (lane & 15)) * 24 + (lane >> 4) * 8) * 2;
                ldsm4(af[i][p], ad);
            }

#pragma unroll
        for (int j2 = 0; j2 < 4; j2++) {
            unsigned bh[4], bl[4];
            uint32_t bd = boff + ((lane & 15) * 520 + w * 64 + j2 * 16 + (lane >> 4) * 8) * 2;
            ldsm4t(bh, bd);
            ldsm4t(bl, bd + 16 * 520 * 2);
#pragma unroll
            for (int i = 0; i < 2; i++) {
                mma16816(acc[i][2 * j2],     af[i][0], bh);       // hi*hi
                mma16816(acc[i][2 * j2],     af[i][0], bl);       // hi*lo
                mma16816(acc[i][2 * j2],     af[i][1], bh);       // lo*hi
                mma16816(acc[i][2 * j2 + 1], af[i][0], bh + 2);
                mma16816(acc[i][2 * j2 + 1], af[i][0], bl + 2);
                mma16816(acc[i][2 * j2 + 1], af[i][1], bh + 2);
            }
        }
        __syncthreads();
    }

    // ---- bias values for this lane's 16 columns -----------------------------
    float bv[8][2];
#pragma unroll
    for (int j = 0; j < 8; j++) {
        int cl = w * 64 + j * 8 + 2 * tig;
        float b0 = bias[coff + cl], b1 = bias[coff + cl + 1];
        if (trow) { b0 += tval * trow[coff + cl]; b1 += tval * trow[coff + cl + 1]; }
        bv[j][0] = b0; bv[j][1] = b1;
    }

    if (mode == 0) {
        float* red = reinterpret_cast<float*>(dyn_sm);
#pragma unroll
        for (int i = 0; i < 2; i++) {
            float sA = 0.f, qA = 0.f, sB = 0.f, qB = 0.f;
#pragma unroll
            for (int j = 0; j < 8; j++) {
                float f0 = acc[i][j][0] + bv[j][0];
                float f1 = acc[i][j][1] + bv[j][1];
                float f2 = acc[i][j][2] + bv[j][0];
                float f3 = acc[i][j][3] + bv[j][1];
                acc[i][j][0] = f0; acc[i][j][1] = f1;
                acc[i][j][2] = f2; acc[i][j][3] = f3;
                sA += f0 + f1; qA += f0 * f0 + f1 * f1;
                sB += f2 + f3; qB += f2 * f2 + f3 * f3;
            }
#pragma unroll
            for (int o = 1; o <= 2; o <<= 1) {
                sA += __shfl_xor_sync(0xffffffffu, sA, o);
                qA += __shfl_xor_sync(0xffffffffu, qA, o);
                sB += __shfl_xor_sync(0xffffffffu, sB, o);
                qB += __shfl_xor_sync(0xffffffffu, qB, o);
            }
            if (tig == 0) {
                int rA = i * 16 + g, rB = i * 16 + 8 + g;
                red[rA * 8 + w] = sA; red[256 + rA * 8 + w] = qA;
                red[rB * 8 + w] = sB; red[256 + rB * 8 + w] = qB;
            }
        }
        __syncthreads();
        if (tid < 32) {
            float s = 0.f, q = 0.f;
#pragma unroll
            for (int k = 0; k < 8; k++) { s += red[tid * 8 + k]; q += red[256 + tid * 8 + k]; }
            float mean = s * (1.f / HID);
            float inv  = rsqrtf(q * (1.f / HID) - mean * mean + 1e-5f);
            red[512 + tid] = mean;
            red[544 + tid] = inv;
        }
        __syncthreads();
#pragma unroll
        for (int i = 0; i < 2; i++)
#pragma unroll
            for (int h = 0; h < 2; h++) {
                int lr = i * 16 + h * 8 + g;
                float mean = red[512 + lr], inv = red[544 + lr];
                size_t base = (size_t)(rowBase + lr) * HID;
#pragma unroll
                for (int j = 0; j < 8; j++) {
                    int cl = w * 64 + j * 8 + 2 * tig;
                    float v0 = (acc[i][j][h * 2 + 0] - mean) * inv * lng[cl] + lnb[cl];
                    float v1 = (acc[i][j][h * 2 + 1] - mean) * inv * lng[cl + 1] + lnb[cl + 1];
                    v0 = v0 > 0.f ? v0 : 0.01f * v0;
                    v1 = v1 > 0.f ? v1 : 0.01f * v1;
                    store_planes(outh, outl, base + cl, v0, v1);
                }
            }
    } else if (mode == 1) {
#pragma unroll
        for (int i = 0; i < 2; i++)
#pragma unroll
            for (int h = 0; h < 2; h++) {
                size_t base = (size_t)(rowBase + i * 16 + h * 8 + g) * ldo + coff;
#pragma unroll
                for (int j = 0; j < 8; j++) {
                    int cl = w * 64 + j * 8 + 2 * tig;
                    float2 v;
                    v.x = acc[i][j][h * 2 + 0] + bv[j][0];
                    v.y = acc[i][j][h * 2 + 1] + bv[j][1];
                    *reinterpret_cast<float2*>(out + base + cl) = v;
                }
            }
    } else {
#pragma unroll
        for (int i = 0; i < 2; i++)
#pragma unroll
            for (int h = 0; h < 2; h++) {
                size_t base = (size_t)(rowBase + i * 16 + h * 8 + g) * HID;
#pragma unroll
                for (int j = 0; j < 8; j++) {
                    int cl = w * 64 + j * 8 + 2 * tig;
                    size_t idx = base + cl;
                    float f0 = acc[i][j][h * 2 + 0] + bv[j][0];
                    float f1 = acc[i][j][h * 2 + 1] + bv[j][1];
                    float2 hv = *reinterpret_cast<const float2*>(Hb + idx);
                    if (mode == 2) {
                        float2 ka; ka.x = f0; ka.y = f1;
                        *reinterpret_cast<float2*>(KACCb + idx) = ka;
                        store_planes(outh, outl, idx, hv.x + 0.125f * f0, hv.y + 0.125f * f1);
                    } else if (mode == 3) {
                        float2 ka = *reinterpret_cast<const float2*>(KACCb + idx);
                        ka.x += 2.f * f0; ka.y += 2.f * f1;
                        *reinterpret_cast<float2*>(KACCb + idx) = ka;
                        store_planes(outh, outl, idx, hv.x + 0.125f * f0, hv.y + 0.125f * f1);
                    } else if (mode == 4) {
                        float2 ka = *reinterpret_cast<const float2*>(KACCb + idx);
                        ka.x += 2.f * f0; ka.y += 2.f * f1;
                        *reinterpret_cast<float2*>(KACCb + idx) = ka;
                        store_planes(outh, outl, idx, hv.x + 0.25f * f0, hv.y + 0.25f * f1);
                    } else {
                        float2 ka = *reinterpret_cast<const float2*>(KACCb + idx);
                        float n0 = hv.x + (0.25f / 6.f) * (ka.x + f0);
                        float n1 = hv.y + (0.25f / 6.f) * (ka.y + f1);
                        float2 hn; hn.x = n0; hn.y = n1;
                        *reinterpret_cast<float2*>(Hb + idx) = hn;
                        store_planes(outh, outl, idx, n0, n1);
                    }
                }
            }
    }
}

// ---------------- GRU gate fusion -------------------------------------------
__global__ void gates_kernel(int t, const float* __restrict__ hp,
                             float* __restrict__ hn,
                             bf16* __restrict__ hnh, bf16* __restrict__ hnl,
                             float* __restrict__ dout) {
    int idx = blockIdx.x * blockDim.x + threadIdx.x;
    if (idx >= BATCH * HID) return;
    int r = idx >> 9;
    int c = idx & 511;
    size_t gib = ((size_t)t * BATCH + r) * GATE3;
    size_t ghb = (size_t)r * GATE3;
    float ir = g_GI[gib + c], iz = g_GI[gib + c + HID], in_ = g_GI[gib + c + 2 * HID];
    float hr = g_GH[ghb + c], hz = g_GH[ghb + c + HID], hnn = g_GH[ghb + c + 2 * HID];
    float rg = 1.f / (1.f + expf(-(ir + hr)));
    float zg = 1.f / (1.f + expf(-(iz + hz)));
    float ng = tanhf(in_ + rg * hnn);
    float h  = hp[idx];
    float v  = (1.f - zg) * ng + zg * h;
    hn[idx] = v;
    bf16 vh = __float2bfloat16(v);
    hnh[idx] = vh;
    hnl[idx] = __float2bfloat16(v - __bfloat162float(vh));
    if (dout) dout[idx] = v;
}

// ---------------- host orchestration ----------------------------------------
extern "C" void kernel_launch(void* const* d_in, const int* in_sizes, int n_in,
                              void* d_out, int out_size) {
    const float* xs       = (const float*)d_in[0];
    const float* obs_W    = (const float*)d_in[1];
    const float* obs_b    = (const float*)d_in[2];
    const float* obs_ln_g = (const float*)d_in[3];
    const float* obs_ln_b = (const float*)d_in[4];
    const float* ode_W1   = (const float*)d_in[5];   // [513,512]
    const float* ode_b1   = (const float*)d_in[6];
    const float* ode_ln1g = (const float*)d_in[7];
    const float* ode_ln1b = (const float*)d_in[8];
    const float* ode_W2   = (const float*)d_in[9];
    const float* ode_b2   = (const float*)d_in[10];
    const float* ode_ln2g = (const float*)d_in[11];
    const float* ode_ln2b = (const float*)d_in[12];
    const float* ode_Wout = (const float*)d_in[13];
    const float* ode_bout = (const float*)d_in[14];
    const float* W_ih     = (const float*)d_in[15];  // [512,1536]
    const float* b_ih     = (const float*)d_in[16];
    const float* W_hh     = (const float*)d_in[17];
    const float* b_hh     = (const float*)d_in[18];

    float *pH, *pKACC, *pGI, *pGH, *pHP0, *pHP1;
    cudaGetSymbolAddress((void**)&pH,    g_H);
    cudaGetSymbolAddress((void**)&pKACC, g_KACC);
    cudaGetSymbolAddress((void**)&pGI,   g_GI);
    cudaGetSymbolAddress((void**)&pGH,   g_GH);
    cudaGetSymbolAddress((void**)&pHP0,  g_HP0);
    cudaGetSymbolAddress((void**)&pHP1,  g_HP1);

    bf16 *pHh, *pHl, *pTh, *pTl, *pZ1h, *pZ1l, *pZ2h, *pZ2l;
    bf16 *pP0h, *pP0l, *pP1h, *pP1l;
    bf16 *pW1h, *pW1l, *pW2h, *pW2l, *pWoh, *pWol, *pWihh, *pWihl, *pWhhh, *pWhhl;
    cudaGetSymbolAddress((void**)&pHh,  g_Hh);   cudaGetSymbolAddress((void**)&pHl,  g_Hl);
    cudaGetSymbolAddress((void**)&pTh,  g_Th);   cudaGetSymbolAddress((void**)&pTl,  g_Tl);
    cudaGetSymbolAddress((void**)&pZ1h, g_Z1h);  cudaGetSymbolAddress((void**)&pZ1l, g_Z1l);
    cudaGetSymbolAddress((void**)&pZ2h, g_Z2h);  cudaGetSymbolAddress((void**)&pZ2l, g_Z2l);
    cudaGetSymbolAddress((void**)&pP0h, g_P0h);  cudaGetSymbolAddress((void**)&pP0l, g_P0l);
    cudaGetSymbolAddress((void**)&pP1h, g_P1h);  cudaGetSymbolAddress((void**)&pP1l, g_P1l);
    cudaGetSymbolAddress((void**)&pW1h, g_W1h);  cudaGetSymbolAddress((void**)&pW1l, g_W1l);
    cudaGetSymbolAddress((void**)&pW2h, g_W2h);  cudaGetSymbolAddress((void**)&pW2l, g_W2l);
    cudaGetSymbolAddress((void**)&pWoh, g_Woh);  cudaGetSymbolAddress((void**)&pWol, g_Wol);
    cudaGetSymbolAddress((void**)&pWihh, g_Wih_h); cudaGetSymbolAddress((void**)&pWihl, g_Wih_l);
    cudaGetSymbolAddress((void**)&pWhhh, g_Whh_h); cudaGetSymbolAddress((void**)&pWhhl, g_Whh_l);

    cudaFuncSetAttribute(gemm_mma, cudaFuncAttributeMaxDynamicSharedMemorySize,
                         SMEM_TOTAL_BYTES);

    // weight splits (first 512x512 of W1; time row stays fp32 via trow path)
    {
        int n = HID * HID;
        split_kernel<<<(n + 255) / 256, 256>>>(ode_W1,   pW1h, pW1l, n);
        split_kernel<<<(n + 255) / 256, 256>>>(ode_W2,   pW2h, pW2l, n);
        split_kernel<<<(n + 255) / 256, 256>>>(ode_Wout, pWoh, pWol, n);
        int m = HID * GATE3;
        split_kernel<<<(m + 255) / 256, 256>>>(W_ih, pWihh, pWihl, m);
        split_kernel<<<(m + 255) / 256, 256>>>(W_hh, pWhhh, pWhhl, m);
    }

    zero_hp0_kernel<<<(BATCH * HID + 255) / 256, 256>>>();
    obs_kernel<<<TB, 256>>>(xs, obs_W, obs_b, obs_ln_g, obs_ln_b);

    const float* trow = ode_W1 + (size_t)512 * 512;
    dim3 gOde(TB / 32, 1);
    const size_t SM = SMEM_TOTAL_BYTES;

    for (int s = 0; s < 4; s++) {
        float t0 = s * 0.25f;
        float tv[4] = {t0, t0 + 0.125f, t0 + 0.125f, t0 + 0.25f};
        int   km[4] = {2, 3, 4, 5};
        for (int e = 0; e < 4; e++) {
            const bf16* Ah = (e == 0) ? pHh : pTh;
            const bf16* Al = (e == 0) ? pHl : pTl;
            // layer 1: LN+leaky, t folded into bias
            gemm_mma<<<gOde, 256, SM>>>(Ah, Al, pW1h, pW1l, HID,
                                        ode_b1, trow, tv[e], ode_ln1g, ode_ln1b,
                                        nullptr, 0, pZ1h, pZ1l, nullptr, nullptr, 0);
            // layer 2
            gemm_mma<<<gOde, 256, SM>>>(pZ1h, pZ1l, pW2h, pW2l, HID,
                                        ode_b2, nullptr, 0.f, ode_ln2g, ode_ln2b,
                                        nullptr, 0, pZ2h, pZ2l, nullptr, nullptr, 0);
            // out layer + RK4 epilogue.
            // k1..k3 (modes 2-4) write TMP planes; k4+combine (mode 5) must
            // write the *H* planes — the next step's k1 and the GI GEMM read them.
            bf16* oh = (km[e] == 5) ? pHh : pTh;
            bf16* ol = (km[e] == 5) ? pHl : pTl;
            gemm_mma<<<gOde, 256, SM>>>(pZ2h, pZ2l, pWoh, pWol, HID,
                                        ode_bout, nullptr, 0.f, nullptr, nullptr,
                                        nullptr, 0, oh, ol, pH, pKACC, km[e]);
        }
    }

    // gi = h_ode @ W_ih + b_ih for all timesteps
    gemm_mma<<<dim3(TB / 32, 3), 256, SM>>>(pHh, pHl, pWihh, pWihl, GATE3,
                                            b_ih, nullptr, 0.f, nullptr, nullptr,
                                            pGI, GATE3, nullptr, nullptr,
                                            nullptr, nullptr, 1);

    // sequential GRU
    for (int t = 0; t < T_STEPS; t++) {
        float* hp = (t & 1) ? pHP1 : pHP0;
        float* hn = (t & 1) ? pHP0 : pHP1;
        bf16* hph = (t & 1) ? pP1h : pP0h;
        bf16* hpl = (t & 1) ? pP1l : pP0l;
        bf16* hnh = (t & 1) ? pP0h : pP1h;
        bf16* hnl = (t & 1) ? pP0l : pP1l;
        gemm_mma<<<dim3(BATCH / 32, 3), 256, SM>>>(hph, hpl, pWhhh, pWhhl, GATE3,
                                                   b_hh, nullptr, 0.f, nullptr, nullptr,
                                                   pGH, GATE3, nullptr, nullptr,
                                                   nullptr, nullptr, 1);
        gates_kernel<<<(BATCH * HID + 255) / 256, 256>>>(
            t, hp, hn, hnh, hnl, (t == T_STEPS - 1) ? (float*)d_out : nullptr);
    }
}

// round 9
// speedup vs baseline: 2.2722x; 1.2830x over previous
#include <cuda_runtime.h>
#include <cuda_bf16.h>
#include <stdint.h>
#include <cstdint>
#include <math.h>

#define T_STEPS 64
#define BATCH   1024
#define OBSD    8
#define HID     512
#define TB      (T_STEPS * BATCH)   /* 65536 */
#define GATE3   (3 * HID)           /* 1536  */

typedef __nv_bfloat16 bf16;

// ---------------- fp32 state ------------------------------------------------
__device__ __align__(128) float g_H   [TB * HID];
__device__ __align__(128) float g_KACC[TB * HID];
__device__ __align__(128) float g_GI  [(size_t)TB * GATE3];
__device__ __align__(128) float g_GH  [BATCH * GATE3];
__device__ __align__(128) float g_HP0 [BATCH * HID];
__device__ __align__(128) float g_HP1 [BATCH * HID];

// ---------------- bf16 hi/lo activation planes ------------------------------
__device__ __align__(128) bf16 g_Hh [TB * HID], g_Hl [TB * HID];
__device__ __align__(128) bf16 g_Th [TB * HID], g_Tl [TB * HID];
__device__ __align__(128) bf16 g_Z1h[TB * HID], g_Z1l[TB * HID];
__device__ __align__(128) bf16 g_Z2h[TB * HID], g_Z2l[TB * HID];
__device__ __align__(128) bf16 g_P0h[BATCH * HID], g_P0l[BATCH * HID];
__device__ __align__(128) bf16 g_P1h[BATCH * HID], g_P1l[BATCH * HID];

// ---------------- bf16 hi/lo weight planes ----------------------------------
__device__ __align__(128) bf16 g_W1h[HID * HID],   g_W1l[HID * HID];
__device__ __align__(128) bf16 g_W2h[HID * HID],   g_W2l[HID * HID];
__device__ __align__(128) bf16 g_Woh[HID * HID],   g_Wol[HID * HID];
__device__ __align__(128) bf16 g_Wih_h[HID * GATE3], g_Wih_l[HID * GATE3];
__device__ __align__(128) bf16 g_Whh_h[HID * GATE3], g_Whh_l[HID * GATE3];

// ---------------- helpers ----------------------------------------------------
__device__ __forceinline__ void store_planes(bf16* __restrict__ ph,
                                             bf16* __restrict__ pl,
                                             size_t idx, float a, float b) {
    bf16 ah = __float2bfloat16(a);
    bf16 bh = __float2bfloat16(b);
    float ar = a - __bfloat162float(ah);
    float br = b - __bfloat162float(bh);
    __nv_bfloat162 vh; vh.x = ah; vh.y = bh;
    __nv_bfloat162 vl; vl.x = __float2bfloat16(ar); vl.y = __float2bfloat16(br);
    *reinterpret_cast<__nv_bfloat162*>(ph + idx) = vh;
    *reinterpret_cast<__nv_bfloat162*>(pl + idx) = vl;
}

__device__ __forceinline__ void mma16816(float* d, const unsigned* a, const unsigned* b) {
    asm volatile(
        "mma.sync.aligned.m16n8k16.row.col.f32.bf16.bf16.f32 "
        "{%0,%1,%2,%3},{%4,%5,%6,%7},{%8,%9},{%0,%1,%2,%3};\n"
        : "+f"(d[0]), "+f"(d[1]), "+f"(d[2]), "+f"(d[3])
        : "r"(a[0]), "r"(a[1]), "r"(a[2]), "r"(a[3]), "r"(b[0]), "r"(b[1]));
}

__device__ __forceinline__ void ldsm4(unsigned* r, uint32_t addr) {
    asm volatile("ldmatrix.sync.aligned.m8n8.x4.shared.b16 {%0,%1,%2,%3},[%4];\n"
                 : "=r"(r[0]), "=r"(r[1]), "=r"(r[2]), "=r"(r[3]) : "r"(addr));
}
__device__ __forceinline__ void ldsm4t(unsigned* r, uint32_t addr) {
    asm volatile("ldmatrix.sync.aligned.m8n8.x4.trans.shared.b16 {%0,%1,%2,%3},[%4];\n"
                 : "=r"(r[0]), "=r"(r[1]), "=r"(r[2]), "=r"(r[3]) : "r"(addr));
}
__device__ __forceinline__ void cp16(uint32_t d, const void* s) {
    asm volatile("cp.async.cg.shared.global [%0], [%1], 16;\n" :: "r"(d), "l"(s));
}
__device__ __forceinline__ void cp_commit() {
    asm volatile("cp.async.commit_group;\n" ::: "memory");
}

// ---------------- weight split ----------------------------------------------
__global__ void split_kernel(const float* __restrict__ src,
                             bf16* __restrict__ hi, bf16* __restrict__ lo, int n) {
    int i = blockIdx.x * blockDim.x + threadIdx.x;
    if (i < n) {
        float x = src[i];
        bf16 h = __float2bfloat16(x);
        hi[i] = h;
        lo[i] = __float2bfloat16(x - __bfloat162float(h));
    }
}

__global__ void zero_hp0_kernel() {
    int i = blockIdx.x * blockDim.x + threadIdx.x;
    if (i < BATCH * HID) {
        g_HP0[i] = 0.f;
        g_P0h[i] = __float2bfloat16(0.f);
        g_P0l[i] = __float2bfloat16(0.f);
    }
}

// ---------------- obs -> hidden ----------------------------------------------
__global__ void obs_kernel(const float* __restrict__ xs,
                           const float* __restrict__ W,
                           const float* __restrict__ b,
                           const float* __restrict__ lng,
                           const float* __restrict__ lnb) {
    int row = blockIdx.x;
    int tid = threadIdx.x;
    __shared__ float xrow[OBSD];
    if (tid < OBSD) xrow[tid] = xs[row * OBSD + tid];
    __syncthreads();

    float y[2];
#pragma unroll
    for (int j = 0; j < 2; j++) {
        int c = tid + j * 256;
        float acc = b[c];
#pragma unroll
        for (int k = 0; k < OBSD; k++) acc += xrow[k] * W[k * HID + c];
        y[j] = acc;
    }
    float s = y[0] + y[1];
    float ss = y[0] * y[0] + y[1] * y[1];
#pragma unroll
    for (int o = 16; o > 0; o >>= 1) {
        s  += __shfl_xor_sync(0xffffffffu, s, o);
        ss += __shfl_xor_sync(0xffffffffu, ss, o);
    }
    __shared__ float rs[8], rss[8];
    int warp = tid >> 5, lane = tid & 31;
    if (lane == 0) { rs[warp] = s; rss[warp] = ss; }
    __syncthreads();
    if (warp == 0) {
        float a  = (lane < 8) ? rs[lane]  : 0.f;
        float b2 = (lane < 8) ? rss[lane] : 0.f;
#pragma unroll
        for (int o = 4; o > 0; o >>= 1) {
            a  += __shfl_xor_sync(0xffffffffu, a, o);
            b2 += __shfl_xor_sync(0xffffffffu, b2, o);
        }
        if (lane == 0) { rs[0] = a; rss[0] = b2; }
    }
    __syncthreads();
    float mean = rs[0] * (1.f / HID);
    float var  = rss[0] * (1.f / HID) - mean * mean;
    float inv  = rsqrtf(var + 1e-5f);
#pragma unroll
    for (int j = 0; j < 2; j++) {
        int c = tid + j * 256;
        float v = (y[j] - mean) * inv * lng[c] + lnb[c];
        v = v > 0.f ? v : 0.01f * v;
        size_t idx = (size_t)row * HID + c;
        g_H[idx] = v;
        bf16 h = __float2bfloat16(v);
        g_Hh[idx] = h;
        g_Hl[idx] = __float2bfloat16(v - __bfloat162float(h));
    }
}

// ---------------- tensor-core GEMM: M=64/CTA, 512 thr, 4-stage pipeline ------
// Warp grid 4x4: warp-row wr owns rows wr*16.., warp-col wc owns cols wc*128..
// Per chunk(BK=16): A frags 2 planes (ldsm4), B 8x(ldsm4t x2 planes), 48 MMAs.
// modes: 0 = LN+leaky -> planes; 1 = fp32 out; 2..5 = RK4 epilogues.
#define A_STAGE     6144                 /* 2 planes * 64 rows * 24 * 2B */
#define STAGE_BYTES 39424                /* A_STAGE + 2*16*520*2        */
#define NSTAGE      4
#define SMEM_TOTAL_BYTES (NSTAGE * STAGE_BYTES)

__device__ __forceinline__ void load_stage(uint32_t smb, int buf, int k0,
                                           const bf16* Ah, const bf16* Al,
                                           const bf16* Wh, const bf16* Wl,
                                           int ldw, int coff, int rowBase, int tid) {
    uint32_t aoff = smb + buf * STAGE_BYTES;
    uint32_t boff = aoff + A_STAGE;
#pragma unroll
    for (int l = 0; l < 4; l++) {
        int idx = tid + l * 512;          // 0..2047
        int p   = idx >> 10;
        int rem = idx & 1023;
        int kr  = rem >> 6;
        int u   = rem & 63;
        const bf16* src = (p ? Wl : Wh) + (size_t)(k0 + kr) * ldw + coff + u * 8;
        cp16(boff + ((p * 16 + kr) * 520 + u * 8) * 2, src);
    }
    if (tid < 256) {
        int p   = tid >> 7;
        int rem = tid & 127;
        int r   = rem >> 1;
        int u   = rem & 1;
        const bf16* src = (p ? Al : Ah) + (size_t)(rowBase + r) * HID + k0 + u * 8;
        cp16(aoff + ((p * 64 + r) * 24 + u * 8) * 2, src);
    }
}

extern __shared__ char dyn_sm[];

__global__ void __launch_bounds__(512, 1)
gemm_mma(const bf16* __restrict__ Ah, const bf16* __restrict__ Al,
         const bf16* __restrict__ Wh, const bf16* __restrict__ Wl, int ldw,
         const float* __restrict__ bias,
         const float* __restrict__ trow, float tval,
         const float* __restrict__ lng, const float* __restrict__ lnb,
         float* __restrict__ out, int ldo,
         bf16* __restrict__ outh, bf16* __restrict__ outl,
         float* __restrict__ Hb, float* __restrict__ KACCb,
         int mode) {
    int tid  = threadIdx.x;
    int w    = tid >> 5;
    int lane = tid & 31;
    int wr   = w >> 2;         // warp row 0..3  -> rows wr*16..wr*16+15
    int wc   = w & 3;          // warp col 0..3  -> cols wc*128..wc*128+127
    int g    = lane >> 2;
    int tig  = lane & 3;
    int rowBase = blockIdx.x * 64;
    int coff    = blockIdx.y * 512;

    uint32_t smb = (uint32_t)__cvta_generic_to_shared(dyn_sm);

    float acc[16][4];
#pragma unroll
    for (int j = 0; j < 16; j++)
#pragma unroll
        for (int q = 0; q < 4; q++) acc[j][q] = 0.f;

    const int NC = HID / 16;   // 32

    // prologue: stages 0,1,2
    load_stage(smb, 0, 0,  Ah, Al, Wh, Wl, ldw, coff, rowBase, tid); cp_commit();
    load_stage(smb, 1, 16, Ah, Al, Wh, Wl, ldw, coff, rowBase, tid); cp_commit();
    load_stage(smb, 2, 32, Ah, Al, Wh, Wl, ldw, coff, rowBase, tid); cp_commit();

#pragma unroll 1
    for (int c = 0; c < NC; c++) {
        asm volatile("cp.async.wait_group 2;\n" ::: "memory");
        __syncthreads();
        if (c + 3 < NC)
            load_stage(smb, (c + 3) & 3, (c + 3) * 16, Ah, Al, Wh, Wl, ldw, coff, rowBase, tid);
        cp_commit();   // always commit: keeps group count uniform

        uint32_t aoff = smb + (c & 3) * STAGE_BYTES;
        uint32_t boff = aoff + A_STAGE;

        unsigned af[2][4];
#pragma unroll
        for (int p = 0; p < 2; p++) {
            uint32_t ad = aoff + ((p * 64 + wr * 16 + (lane & 15)) * 24 + (lane >> 4) * 8) * 2;
            ldsm4(af[p], ad);
        }
#pragma unroll
        for (int j2 = 0; j2 < 8; j2++) {
            unsigned bh[4], bl[4];
            uint32_t bd = boff + ((lane & 15) * 520 + wc * 128 + j2 * 16 + (lane >> 4) * 8) * 2;
            ldsm4t(bh, bd);
            ldsm4t(bl, bd + 16 * 520 * 2);
            mma16816(acc[2 * j2],     af[0], bh);
            mma16816(acc[2 * j2],     af[0], bl);
            mma16816(acc[2 * j2],     af[1], bh);
            mma16816(acc[2 * j2 + 1], af[0], bh + 2);
            mma16816(acc[2 * j2 + 1], af[0], bl + 2);
            mma16816(acc[2 * j2 + 1], af[1], bh + 2);
        }
    }

    if (mode == 0) {
        // fused LayerNorm over full 512-col rows (4 warp-cols cooperate via smem)
        float* red = reinterpret_cast<float*>(dyn_sm);
        float s0 = 0.f, q0 = 0.f, s1 = 0.f, q1 = 0.f;
#pragma unroll
        for (int jt = 0; jt < 16; jt++) {
            int cl = wc * 128 + jt * 8 + 2 * tig;
            float b0 = bias[coff + cl], b1 = bias[coff + cl + 1];
            if (trow) { b0 += tval * trow[coff + cl]; b1 += tval * trow[coff + cl + 1]; }
            float f0 = acc[jt][0] + b0, f1 = acc[jt][1] + b1;
            float f2 = acc[jt][2] + b0, f3 = acc[jt][3] + b1;
            acc[jt][0] = f0; acc[jt][1] = f1; acc[jt][2] = f2; acc[jt][3] = f3;
            s0 += f0 + f1; q0 += f0 * f0 + f1 * f1;
            s1 += f2 + f3; q1 += f2 * f2 + f3 * f3;
        }
#pragma unroll
        for (int o = 1; o <= 2; o <<= 1) {
            s0 += __shfl_xor_sync(0xffffffffu, s0, o);
            q0 += __shfl_xor_sync(0xffffffffu, q0, o);
            s1 += __shfl_xor_sync(0xffffffffu, s1, o);
            q1 += __shfl_xor_sync(0xffffffffu, q1, o);
        }
        if (tig == 0) {
            int r0 = wr * 16 + g, r1 = wr * 16 + 8 + g;
            red[r0 * 4 + wc] = s0; red[256 + r0 * 4 + wc] = q0;
            red[r1 * 4 + wc] = s1; red[256 + r1 * 4 + wc] = q1;
        }
        __syncthreads();
        if (tid < 64) {
            float s = 0.f, q = 0.f;
#pragma unroll
            for (int k = 0; k < 4; k++) { s += red[tid * 4 + k]; q += red[256 + tid * 4 + k]; }
            float mean = s * (1.f / HID);
            float inv  = rsqrtf(q * (1.f / HID) - mean * mean + 1e-5f);
            red[512 + tid] = mean;
            red[576 + tid] = inv;
        }
        __syncthreads();
#pragma unroll
        for (int h = 0; h < 2; h++) {
            int lr = wr * 16 + h * 8 + g;
            float mean = red[512 + lr], inv = red[576 + lr];
            size_t base = (size_t)(rowBase + lr) * HID;
#pragma unroll
            for (int jt = 0; jt < 16; jt++) {
                int cl = wc * 128 + jt * 8 + 2 * tig;
                float v0 = (acc[jt][h * 2 + 0] - mean) * inv * lng[cl] + lnb[cl];
                float v1 = (acc[jt][h * 2 + 1] - mean) * inv * lng[cl + 1] + lnb[cl + 1];
                v0 = v0 > 0.f ? v0 : 0.01f * v0;
                v1 = v1 > 0.f ? v1 : 0.01f * v1;
                store_planes(outh, outl, base + cl, v0, v1);
            }
        }
    } else if (mode == 1) {
#pragma unroll
        for (int h = 0; h < 2; h++) {
            size_t base = (size_t)(rowBase + wr * 16 + h * 8 + g) * ldo + coff;
#pragma unroll
            for (int jt = 0; jt < 16; jt++) {
                int cl = wc * 128 + jt * 8 + 2 * tig;
                float b0 = bias[coff + cl], b1 = bias[coff + cl + 1];
                float2 v;
                v.x = acc[jt][h * 2 + 0] + b0;
                v.y = acc[jt][h * 2 + 1] + b1;
                *reinterpret_cast<float2*>(out + base + cl) = v;
            }
        }
    } else {
#pragma unroll
        for (int h = 0; h < 2; h++) {
            size_t base = (size_t)(rowBase + wr * 16 + h * 8 + g) * HID;
#pragma unroll
            for (int jt = 0; jt < 16; jt++) {
                int cl = wc * 128 + jt * 8 + 2 * tig;
                size_t idx = base + cl;
                float b0 = bias[coff + cl], b1 = bias[coff + cl + 1];
                float f0 = acc[jt][h * 2 + 0] + b0;
                float f1 = acc[jt][h * 2 + 1] + b1;
                float2 hv = *reinterpret_cast<const float2*>(Hb + idx);
                if (mode == 2) {
                    float2 ka; ka.x = f0; ka.y = f1;
                    *reinterpret_cast<float2*>(KACCb + idx) = ka;
                    store_planes(outh, outl, idx, hv.x + 0.125f * f0, hv.y + 0.125f * f1);
                } else if (mode == 3) {
                    float2 ka = *reinterpret_cast<const float2*>(KACCb + idx);
                    ka.x += 2.f * f0; ka.y += 2.f * f1;
                    *reinterpret_cast<float2*>(KACCb + idx) = ka;
                    store_planes(outh, outl, idx, hv.x + 0.125f * f0, hv.y + 0.125f * f1);
                } else if (mode == 4) {
                    float2 ka = *reinterpret_cast<const float2*>(KACCb + idx);
                    ka.x += 2.f * f0; ka.y += 2.f * f1;
                    *reinterpret_cast<float2*>(KACCb + idx) = ka;
                    store_planes(outh, outl, idx, hv.x + 0.25f * f0, hv.y + 0.25f * f1);
                } else {
                    float2 ka = *reinterpret_cast<const float2*>(KACCb + idx);
                    float n0 = hv.x + (0.25f / 6.f) * (ka.x + f0);
                    float n1 = hv.y + (0.25f / 6.f) * (ka.y + f1);
                    float2 hn; hn.x = n0; hn.y = n1;
                    *reinterpret_cast<float2*>(Hb + idx) = hn;
                    store_planes(outh, outl, idx, n0, n1);
                }
            }
        }
    }
}

// ---------------- GRU gate fusion -------------------------------------------
__global__ void gates_kernel(int t, const float* __restrict__ hp,
                             float* __restrict__ hn,
                             bf16* __restrict__ hnh, bf16* __restrict__ hnl,
                             float* __restrict__ dout) {
    int idx = blockIdx.x * blockDim.x + threadIdx.x;
    if (idx >= BATCH * HID) return;
    int r = idx >> 9;
    int c = idx & 511;
    size_t gib = ((size_t)t * BATCH + r) * GATE3;
    size_t ghb = (size_t)r * GATE3;
    float ir = g_GI[gib + c], iz = g_GI[gib + c + HID], in_ = g_GI[gib + c + 2 * HID];
    float hr = g_GH[ghb + c], hz = g_GH[ghb + c + HID], hnn = g_GH[ghb + c + 2 * HID];
    float rg = 1.f / (1.f + expf(-(ir + hr)));
    float zg = 1.f / (1.f + expf(-(iz + hz)));
    float ng = tanhf(in_ + rg * hnn);
    float h  = hp[idx];
    float v  = (1.f - zg) * ng + zg * h;
    hn[idx] = v;
    bf16 vh = __float2bfloat16(v);
    hnh[idx] = vh;
    hnl[idx] = __float2bfloat16(v - __bfloat162float(vh));
    if (dout) dout[idx] = v;
}

// ---------------- host orchestration ----------------------------------------
extern "C" void kernel_launch(void* const* d_in, const int* in_sizes, int n_in,
                              void* d_out, int out_size) {
    const float* xs       = (const float*)d_in[0];
    const float* obs_W    = (const float*)d_in[1];
    const float* obs_b    = (const float*)d_in[2];
    const float* obs_ln_g = (const float*)d_in[3];
    const float* obs_ln_b = (const float*)d_in[4];
    const float* ode_W1   = (const float*)d_in[5];   // [513,512]
    const float* ode_b1   = (const float*)d_in[6];
    const float* ode_ln1g = (const float*)d_in[7];
    const float* ode_ln1b = (const float*)d_in[8];
    const float* ode_W2   = (const float*)d_in[9];
    const float* ode_b2   = (const float*)d_in[10];
    const float* ode_ln2g = (const float*)d_in[11];
    const float* ode_ln2b = (const float*)d_in[12];
    const float* ode_Wout = (const float*)d_in[13];
    const float* ode_bout = (const float*)d_in[14];
    const float* W_ih     = (const float*)d_in[15];  // [512,1536]
    const float* b_ih     = (const float*)d_in[16];
    const float* W_hh     = (const float*)d_in[17];
    const float* b_hh     = (const float*)d_in[18];

    float *pH, *pKACC, *pGI, *pGH, *pHP0, *pHP1;
    cudaGetSymbolAddress((void**)&pH,    g_H);
    cudaGetSymbolAddress((void**)&pKACC, g_KACC);
    cudaGetSymbolAddress((void**)&pGI,   g_GI);
    cudaGetSymbolAddress((void**)&pGH,   g_GH);
    cudaGetSymbolAddress((void**)&pHP0,  g_HP0);
    cudaGetSymbolAddress((void**)&pHP1,  g_HP1);

    bf16 *pHh, *pHl, *pTh, *pTl, *pZ1h, *pZ1l, *pZ2h, *pZ2l;
    bf16 *pP0h, *pP0l, *pP1h, *pP1l;
    bf16 *pW1h, *pW1l, *pW2h, *pW2l, *pWoh, *pWol, *pWihh, *pWihl, *pWhhh, *pWhhl;
    cudaGetSymbolAddress((void**)&pHh,  g_Hh);   cudaGetSymbolAddress((void**)&pHl,  g_Hl);
    cudaGetSymbolAddress((void**)&pTh,  g_Th);   cudaGetSymbolAddress((void**)&pTl,  g_Tl);
    cudaGetSymbolAddress((void**)&pZ1h, g_Z1h);  cudaGetSymbolAddress((void**)&pZ1l, g_Z1l);
    cudaGetSymbolAddress((void**)&pZ2h, g_Z2h);  cudaGetSymbolAddress((void**)&pZ2l, g_Z2l);
    cudaGetSymbolAddress((void**)&pP0h, g_P0h);  cudaGetSymbolAddress((void**)&pP0l, g_P0l);
    cudaGetSymbolAddress((void**)&pP1h, g_P1h);  cudaGetSymbolAddress((void**)&pP1l, g_P1l);
    cudaGetSymbolAddress((void**)&pW1h, g_W1h);  cudaGetSymbolAddress((void**)&pW1l, g_W1l);
    cudaGetSymbolAddress((void**)&pW2h, g_W2h);  cudaGetSymbolAddress((void**)&pW2l, g_W2l);
    cudaGetSymbolAddress((void**)&pWoh, g_Woh);  cudaGetSymbolAddress((void**)&pWol, g_Wol);
    cudaGetSymbolAddress((void**)&pWihh, g_Wih_h); cudaGetSymbolAddress((void**)&pWihl, g_Wih_l);
    cudaGetSymbolAddress((void**)&pWhhh, g_Whh_h); cudaGetSymbolAddress((void**)&pWhhl, g_Whh_l);

    cudaFuncSetAttribute(gemm_mma, cudaFuncAttributeMaxDynamicSharedMemorySize,
                         SMEM_TOTAL_BYTES);

    {
        int n = HID * HID;
        split_kernel<<<(n + 255) / 256, 256>>>(ode_W1,   pW1h, pW1l, n);
        split_kernel<<<(n + 255) / 256, 256>>>(ode_W2,   pW2h, pW2l, n);
        split_kernel<<<(n + 255) / 256, 256>>>(ode_Wout, pWoh, pWol, n);
        int m = HID * GATE3;
        split_kernel<<<(m + 255) / 256, 256>>>(W_ih, pWihh, pWihl, m);
        split_kernel<<<(m + 255) / 256, 256>>>(W_hh, pWhhh, pWhhl, m);
    }

    zero_hp0_kernel<<<(BATCH * HID + 255) / 256, 256>>>();
    obs_kernel<<<TB, 256>>>(xs, obs_W, obs_b, obs_ln_g, obs_ln_b);

    const float* trow = ode_W1 + (size_t)512 * 512;
    dim3 gOde(TB / 64, 1);
    const size_t SM = SMEM_TOTAL_BYTES;

    for (int s = 0; s < 4; s++) {
        float t0 = s * 0.25f;
        float tv[4] = {t0, t0 + 0.125f, t0 + 0.125f, t0 + 0.25f};
        int   km[4] = {2, 3, 4, 5};
        for (int e = 0; e < 4; e++) {
            const bf16* Ah = (e == 0) ? pHh : pTh;
            const bf16* Al = (e == 0) ? pHl : pTl;
            gemm_mma<<<gOde, 512, SM>>>(Ah, Al, pW1h, pW1l, HID,
                                        ode_b1, trow, tv[e], ode_ln1g, ode_ln1b,
                                        nullptr, 0, pZ1h, pZ1l, nullptr, nullptr, 0);
            gemm_mma<<<gOde, 512, SM>>>(pZ1h, pZ1l, pW2h, pW2l, HID,
                                        ode_b2, nullptr, 0.f, ode_ln2g, ode_ln2b,
                                        nullptr, 0, pZ2h, pZ2l, nullptr, nullptr, 0);
            // k4+combine (mode 5) writes the H planes (read by next k1 / GI GEMM)
            bf16* oh = (km[e] == 5) ? pHh : pTh;
            bf16* ol = (km[e] == 5) ? pHl : pTl;
            gemm_mma<<<gOde, 512, SM>>>(pZ2h, pZ2l, pWoh, pWol, HID,
                                        ode_bout, nullptr, 0.f, nullptr, nullptr,
                                        nullptr, 0, oh, ol, pH, pKACC, km[e]);
        }
    }

    // gi = h_ode @ W_ih + b_ih for all timesteps
    gemm_mma<<<dim3(TB / 64, 3), 512, SM>>>(pHh, pHl, pWihh, pWihl, GATE3,
                                            b_ih, nullptr, 0.f, nullptr, nullptr,
                                            pGI, GATE3, nullptr, nullptr,
                                            nullptr, nullptr, 1);

    // sequential GRU
    for (int t = 0; t < T_STEPS; t++) {
        float* hp = (t & 1) ? pHP1 : pHP0;
        float* hn = (t & 1) ? pHP0 : pHP1;
        bf16* hph = (t & 1) ? pP1h : pP0h;
        bf16* hpl = (t & 1) ? pP1l : pP0l;
        bf16* hnh = (t & 1) ? pP0h : pP1h;
        bf16* hnl = (t & 1) ? pP0l : pP1l;
        gemm_mma<<<dim3(BATCH / 64, 3), 512, SM>>>(hph, hpl, pWhhh, pWhhl, GATE3,
                                                   b_hh, nullptr, 0.f, nullptr, nullptr,
                                                   pGH, GATE3, nullptr, nullptr,
                                                   nullptr, nullptr, 1);
        gates_kernel<<<(BATCH * HID + 255) / 256, 256>>>(
            t, hp, hn, hnh, hnl, (t == T_STEPS - 1) ? (float*)d_out : nullptr);
    }
}